// round 2
// baseline (speedup 1.0000x reference)
#include <cuda_runtime.h>
#include <math.h>

#define BB 4
#define CC 64
#define OO 64
#define HH 128
#define WW 128
#define HW (HH*WW)
#define K2 9
#define CK (CC*K2)   // 576

#define FMA2(d, a, b) asm("fma.rn.f32x2 %0, %1, %2, %0;" : "+l"(d) : "l"(a), "l"(b))
#define PACK2(d, s)   asm("mov.b64 %0, {%1, %1};" : "=l"(d) : "r"(__float_as_uint(s)))

// Scratch: offset-conv output. Channels 0..8 = off_x, 9..17 = off_y, 18..26 = sigmoid(mask).
__device__ float g_om[BB * 27 * HW];

// ---------------------------------------------------------------------------
// Kernel A: 3x3 conv feat -> 27 ch (off_x, off_y, sigmoid(mask)) into g_om.
// 256 threads: half h handles input-channel chunk h (32 channels), 27 accs
// each (f32x2-packed, padded to 28), SMEM reduction at the end.
// Weights for both chunks staged once in dynamic SMEM as [chunk][cl*9+kk][28].
// ---------------------------------------------------------------------------
__global__ __launch_bounds__(256) void off_conv_kernel(
    const float* __restrict__ feat,
    const float* __restrict__ w_off,
    const float* __restrict__ b_off)
{
    extern __shared__ float smem[];
    float* sw  = smem;                 // 2 * 288 * 28 floats
    float* red = smem + 2 * 288 * 28;  // 128 * 29 floats (pad 29: conflict-free)

    const int tid  = threadIdx.x;
    const int half = tid >> 7;         // which 32-channel chunk
    const int lpx  = tid & 127;
    const int b    = blockIdx.y;
    const int pix  = blockIdx.x * 128 + lpx;
    const int y    = pix >> 7;
    const int x    = pix & 127;

    // stage weights for both chunks
    const int PER = 288 * 28;
    for (int i = tid; i < 2 * PER; i += 256) {
        int ch = (i >= PER);
        int r  = i - ch * PER;
        int oc = r % 28;
        int ck = r / 28;               // cl*9 + kk within chunk
        sw[i] = (oc < 27) ? w_off[oc * CK + ch * 288 + ck] : 0.f;
    }
    __syncthreads();

    unsigned long long acc2[14];
#pragma unroll
    for (int i = 0; i < 14; i++) acc2[i] = 0ull;

    const float* fb = feat + ((size_t)b * CC + half * 32) * HW;
    const ulonglong2* swp = (const ulonglong2*)(sw + half * PER);

    for (int cl = 0; cl < 32; cl++) {
        const float* fp = fb + (size_t)cl * HW;
#pragma unroll
        for (int ky = 0; ky < 3; ky++) {
            const int yy   = y + ky - 1;
            const bool yok = ((unsigned)yy < HH);
#pragma unroll
            for (int kx = 0; kx < 3; kx++) {
                const int xx = x + kx - 1;
                float v = (yok && (unsigned)xx < WW) ? __ldg(fp + yy * WW + xx) : 0.f;
                unsigned long long vv; PACK2(vv, v);
                const ulonglong2* w = swp + (cl * 9 + ky * 3 + kx) * 7;
#pragma unroll
                for (int j = 0; j < 7; j++) {
                    ulonglong2 wv = w[j];
                    FMA2(acc2[2 * j],     vv, wv.x);
                    FMA2(acc2[2 * j + 1], vv, wv.y);
                }
            }
        }
    }

    // reduce across the two halves
    if (half == 0) {
#pragma unroll
        for (int j = 0; j < 14; j++) {
            int oc = j * 2;
            if (oc < 27)     red[lpx * 29 + oc]     = __uint_as_float((unsigned)(acc2[j] & 0xffffffffull));
            if (oc + 1 < 27) red[lpx * 29 + oc + 1] = __uint_as_float((unsigned)(acc2[j] >> 32));
        }
    }
    __syncthreads();
    if (half == 1) {
        float* omb = g_om + (size_t)b * 27 * HW;
#pragma unroll
        for (int j = 0; j < 14; j++) {
#pragma unroll
            for (int s = 0; s < 2; s++) {
                int oc = j * 2 + s;
                if (oc >= 27) continue;
                float a = s ? __uint_as_float((unsigned)(acc2[j] >> 32))
                            : __uint_as_float((unsigned)(acc2[j] & 0xffffffffull));
                float z = a + red[lpx * 29 + oc] + __ldg(b_off + oc);
                if (oc >= 18) z = 1.f / (1.f + expf(-z));
                omb[oc * HW + pix] = z;
            }
        }
    }
}

// ---------------------------------------------------------------------------
// Kernel B: fused deformable sampling + GEMM + bias + relu.
// 256 threads per block (one image row of 128 px): half h computes output
// channels [h*32, h*32+32). 32 accumulators/thread as 16 f32x2 pairs.
// Per tap: weights [c][o] staged in SMEM; c-loop unrolled by 2 with all 8
// gathers batched for MLP; 8x LDS.128 + 16x FMA2 per channel.
// ---------------------------------------------------------------------------
__global__ __launch_bounds__(256, 3) void deform_kernel(
    const float* __restrict__ x,
    const float* __restrict__ w_def,
    const float* __restrict__ b_def,
    float* __restrict__ out)
{
    __shared__ float sw[CC * OO];   // [c][o], 16 KB, restaged per tap

    const int tid  = threadIdx.x;
    const int half = tid >> 7;
    const int xo   = tid & 127;
    const int bidx = blockIdx.x;
    const int b    = bidx >> 7;
    const int y    = bidx & 127;
    const int pix  = y * WW + xo;
    const int obase = half * 32;

    unsigned long long acc2[16];
#pragma unroll
    for (int i = 0; i < 16; i++) acc2[i] = 0ull;

    const float* xb  = x + (size_t)b * CC * HW;
    const float* omb = g_om + (size_t)b * 27 * HW;

    for (int tap = 0; tap < 9; tap++) {
        __syncthreads();
        for (int i = tid; i < CC * OO; i += 256) {
            int c = i >> 6, o = i & 63;
            sw[i] = w_def[o * CK + c * K2 + tap];
        }
        __syncthreads();

        const float offx = omb[(tap)      * HW + pix];
        const float offy = omb[(9  + tap) * HW + pix];
        const float m    = omb[(18 + tap) * HW + pix];

        const int dy = tap / 3 - 1;
        const int dx = tap % 3 - 1;
        const float ys = (float)(y  + dy) + offy;
        const float xs = (float)(xo + dx) + offx;

        const float y0f = floorf(ys), x0f = floorf(xs);
        const float wy1 = ys - y0f,  wx1 = xs - x0f;
        const float wy0 = 1.f - wy1, wx0 = 1.f - wx1;

        const int iy0 = (int)y0f, ix0 = (int)x0f;
        const int iy1 = iy0 + 1,  ix1 = ix0 + 1;
        const bool vy0 = ((unsigned)iy0 < HH), vy1 = ((unsigned)iy1 < HH);
        const bool vx0 = ((unsigned)ix0 < WW), vx1 = ((unsigned)ix1 < WW);

        const float w00 = (vy0 && vx0) ? wy0 * wx0 * m : 0.f;
        const float w01 = (vy0 && vx1) ? wy0 * wx1 * m : 0.f;
        const float w10 = (vy1 && vx0) ? wy1 * wx0 * m : 0.f;
        const float w11 = (vy1 && vx1) ? wy1 * wx1 * m : 0.f;

        const int cy0 = min(max(iy0, 0), HH - 1), cy1 = min(max(iy1, 0), HH - 1);
        const int cx0 = min(max(ix0, 0), WW - 1), cx1 = min(max(ix1, 0), WW - 1);
        const int i00 = cy0 * WW + cx0, i01 = cy0 * WW + cx1;
        const int i10 = cy1 * WW + cx0, i11 = cy1 * WW + cx1;

        const ulonglong2* swv = (const ulonglong2*)sw + half * 8;
#pragma unroll 1
        for (int c0 = 0; c0 < CC; c0 += 2) {
            // batch the 8 gathers for both channels (MLP)
            const float* xp0 = xb + (size_t)c0 * HW;
            const float* xp1 = xp0 + HW;
            float p00 = __ldg(xp0 + i00), p01 = __ldg(xp0 + i01);
            float p02 = __ldg(xp0 + i10), p03 = __ldg(xp0 + i11);
            float p10 = __ldg(xp1 + i00), p11 = __ldg(xp1 + i01);
            float p12 = __ldg(xp1 + i10), p13 = __ldg(xp1 + i11);

            float v0 = w00 * p00 + w01 * p01 + w10 * p02 + w11 * p03;
            float v1 = w00 * p10 + w01 * p11 + w10 * p12 + w11 * p13;
            unsigned long long vv0, vv1;
            PACK2(vv0, v0);
            PACK2(vv1, v1);

            const ulonglong2* wr0 = swv + (size_t)c0 * 16;
            const ulonglong2* wr1 = wr0 + 16;
#pragma unroll
            for (int j = 0; j < 8; j++) {
                ulonglong2 wv0 = wr0[j];
                FMA2(acc2[2 * j],     vv0, wv0.x);
                FMA2(acc2[2 * j + 1], vv0, wv0.y);
            }
#pragma unroll
            for (int j = 0; j < 8; j++) {
                ulonglong2 wv1 = wr1[j];
                FMA2(acc2[2 * j],     vv1, wv1.x);
                FMA2(acc2[2 * j + 1], vv1, wv1.y);
            }
        }
    }

    float* ob = out + (size_t)b * OO * HW;
#pragma unroll
    for (int j = 0; j < 8; j++) {
#pragma unroll
        for (int s = 0; s < 4; s++) {
            int ol = j * 4 + s;
            unsigned long long a = acc2[2 * j + (s >> 1)];
            float z = (s & 1) ? __uint_as_float((unsigned)(a >> 32))
                              : __uint_as_float((unsigned)(a & 0xffffffffull));
            int o = obase + ol;
            z += __ldg(b_def + o);
            ob[(size_t)o * HW + pix] = fmaxf(z, 0.f);
        }
    }
}

extern "C" void kernel_launch(void* const* d_in, const int* in_sizes, int n_in,
                              void* d_out, int out_size) {
    const float* x     = (const float*)d_in[0];
    const float* feat  = (const float*)d_in[1];
    const float* w_off = (const float*)d_in[2];
    const float* b_off = (const float*)d_in[3];
    const float* w_def = (const float*)d_in[4];
    const float* b_def = (const float*)d_in[5];
    float* out = (float*)d_out;

    const int off_smem = (2 * 288 * 28 + 128 * 29) * sizeof(float);  // ~79.4 KB
    cudaFuncSetAttribute(off_conv_kernel,
                         cudaFuncAttributeMaxDynamicSharedMemorySize, off_smem);

    dim3 gA(HW / 128, BB);
    off_conv_kernel<<<gA, 256, off_smem>>>(feat, w_off, b_off);
    deform_kernel<<<BB * HH, 256>>>(x, w_def, b_def, out);
}